// round 15
// baseline (speedup 1.0000x reference)
#include <cuda_runtime.h>

// Problem constants
#define BB   8
#define SEQ  2047
#define LL   2048     // SEQ + 1 (CLS prepended)
#define HH   256
#define NH   8
#define DD   32
#define VV   32001
#define NCH  64       // t-chunks for ybar
#define CHT  32       // tokens per chunk

// ---------------- scratch (static device globals; no allocation) -------------
__device__ int   g_is64;
__device__ float g_qk[NH * HH];                 // per-head folded query vectors (scaled)
__device__ float g_zp[BB * NH * NCH];           // partition-function partials
__device__ float g_ybp[NCH * BB * NH * HH];     // weighted-sum partials (4 MB)
__device__ float g_yfin[BB * HH];               // final hidden at position 0 (accum)

// ---------------- k_init: dtype detect (block 8) + per-head qk (blocks 0-7) --
// Block n also seeds g_yfin[b=n] with the 2*y0 residual (atomic target).
__global__ void __launch_bounds__(256) k_init(const unsigned int* __restrict__ xw,
                                              const float* __restrict__ emb,
                                              const float* __restrict__ wq,
                                              const float* __restrict__ wk) {
    int blk = blockIdx.x;
    int tid = threadIdx.x;

    if (blk == NH) {             // ---- dtype detection ----
        __shared__ int bad;
        if (tid == 0) bad = 0;
        __syncthreads();
        for (int i = tid; i < 1024; i += 256)
            if (xw[2 * i + 1] != 0u) bad = 1;
        __syncthreads();
        if (tid == 0) g_is64 = bad ? 0 : 1;
        return;
    }

    int n = blk;
    __shared__ float y0s[HH];
    __shared__ float q0s[DD];

    float y0 = emb[2 * HH + tid] + ((tid & 1) ? 1.0f : 0.0f);   // pe[0]=[0,1,0,1..]
    y0s[tid] = y0;
    g_yfin[n * HH + tid] = 2.f * y0;      // seed residual for batch b=n
    __syncthreads();

    if (tid < DD) {
        const float* wqr = wq + (size_t)(n * DD + tid) * HH;
        float a = 0.f;
        #pragma unroll 8
        for (int h = 0; h < HH; h++) a += y0s[h] * wqr[h];
        q0s[tid] = a;
    }
    __syncthreads();

    const float scale = 0.17677669529663687f;   // 1/sqrt(32)
    float s = 0.f;
    #pragma unroll
    for (int k = 0; k < DD; k++)
        s += q0s[k] * wk[(size_t)(n * DD + k) * HH + tid];
    g_qk[n * HH + tid] = s * scale;
}

// ---------------- k_ybar: gather y (emb + inline PE), scores+exp, Z, sums -----
// grid (NCH=64 chunks, BB batches), 256 threads; ~42 KB smem
__global__ void __launch_bounds__(256) k_ybar(const void* __restrict__ xraw,
                                              const float* __restrict__ emb) {
    __shared__ __align__(16) float ys[CHT * HH];   // 32 KB: y = emb[tok] + pe
    __shared__ __align__(16) float qks[NH * HH];   // 8 KB
    __shared__ __align__(16) float A8[NH][CHT];    // 1 KB unnormalized probs
    __shared__ int toks[CHT];
    int tid = threadIdx.x, lane = tid & 31, warp = tid >> 5;
    int ch = blockIdx.x;
    int b  = blockIdx.y;
    int c0 = ch * CHT;
    int is64 = g_is64;

    for (int i = tid; i < NH * HH; i += 256) qks[i] = g_qk[i];
    if (tid < CHT) {
        int t = c0 + tid;
        int tok;
        if (t == 0) tok = 2;
        else if (is64) tok = (int)((const long long*)xraw)[(size_t)b * SEQ + t - 1];
        else           tok = ((const int*)xraw)[(size_t)b * SEQ + t - 1];
        toks[tid] = tok;
    }
    __syncthreads();

    // Phase A: gather emb rows + compute PE inline (coalesced float4)
    {
        const float4* emb4 = (const float4*)emb;
        float4* ys4        = (float4*)ys;
        const float KK = 0.03597789203f;    // ln(10000)/256
        int q = tid & 63;
        float d0 = expf(-(float)(4 * q)     * KK);
        float d1 = expf(-(float)(4 * q + 2) * KK);
        #pragma unroll
        for (int j = tid; j < CHT * 64; j += 256) {
            int r = j >> 6;
            float4 e = emb4[(size_t)toks[r] * 64 + q];
            float t = (float)(c0 + r);
            float s0, cc0, s1, cc1;
            sincosf(t * d0, &s0, &cc0);
            sincosf(t * d1, &s1, &cc1);
            e.x += s0; e.y += cc0; e.z += s1; e.w += cc1;
            ys4[j] = e;
        }
    }
    __syncthreads();

    // Phase B: scores + exp. Warp w handles tokens w*4..w*4+3, all 8 heads.
    {
        const float4* ysq = (const float4*)ys;
        float4 av[4], bv[4];
        #pragma unroll
        for (int r = 0; r < 4; r++) {
            av[r] = ysq[(warp * 4 + r) * 64 + lane];
            bv[r] = ysq[(warp * 4 + r) * 64 + lane + 32];
        }
        float p[4][8];
        #pragma unroll
        for (int n = 0; n < 8; n++) {
            const float4* q4 = (const float4*)(qks + n * HH);
            float4 qa = q4[lane], qb = q4[lane + 32];
            #pragma unroll
            for (int r = 0; r < 4; r++) {
                p[r][n] = av[r].x * qa.x + av[r].y * qa.y + av[r].z * qa.z + av[r].w * qa.w
                        + bv[r].x * qb.x + bv[r].y * qb.y + bv[r].z * qb.z + bv[r].w * qb.w;
            }
        }
        #pragma unroll
        for (int r = 0; r < 4; r++) {
            #pragma unroll
            for (int n = 0; n < 4; n++) {
                bool hi = (lane & 8) != 0;
                float k = hi ? p[r][n + 4] : p[r][n];
                float s = hi ? p[r][n] : p[r][n + 4];
                p[r][n] = k + __shfl_xor_sync(~0u, s, 8);
            }
            #pragma unroll
            for (int n = 0; n < 2; n++) {
                bool hi = (lane & 4) != 0;
                float k = hi ? p[r][n + 2] : p[r][n];
                float s = hi ? p[r][n] : p[r][n + 2];
                p[r][n] = k + __shfl_xor_sync(~0u, s, 4);
            }
            {
                bool hi = (lane & 2) != 0;
                float k = hi ? p[r][1] : p[r][0];
                float s = hi ? p[r][0] : p[r][1];
                p[r][0] = k + __shfl_xor_sync(~0u, s, 2);
            }
            p[r][0] += __shfl_xor_sync(~0u, p[r][0], 16);
            p[r][0] += __shfl_xor_sync(~0u, p[r][0], 1);
        }
        int n_ = lane & 7, r_ = lane >> 3;
        float res[4];
        #pragma unroll
        for (int r = 0; r < 4; r++)
            res[r] = __shfl_sync(~0u, p[r][0], n_ * 2);
        A8[n_][warp * 4 + r_] = expf(res[r_]);
    }
    __syncthreads();

    // Phase Z: warp n reduces A8[n][:]
    {
        float z = A8[warp][lane];
        #pragma unroll
        for (int off = 16; off; off >>= 1) z += __shfl_xor_sync(~0u, z, off);
        if (lane == 0) g_zp[((size_t)b * NH + warp) * NCH + ch] = z;
    }

    // Phase C: weighted sums from smem (tid = h), float4 A8 loads
    int h = tid;
    float acc[8] = {0.f, 0.f, 0.f, 0.f, 0.f, 0.f, 0.f, 0.f};
    const float4* A84 = (const float4*)A8;
    #pragma unroll
    for (int tg = 0; tg < CHT / 4; tg++) {
        float4 a[8];
        #pragma unroll
        for (int n = 0; n < 8; n++) a[n] = A84[n * (CHT / 4) + tg];
        float y0v = ys[(tg * 4 + 0) * HH + h];
        float y1v = ys[(tg * 4 + 1) * HH + h];
        float y2v = ys[(tg * 4 + 2) * HH + h];
        float y3v = ys[(tg * 4 + 3) * HH + h];
        #pragma unroll
        for (int n = 0; n < 8; n++)
            acc[n] += a[n].x * y0v + a[n].y * y1v + a[n].z * y2v + a[n].w * y3v;
    }
    #pragma unroll
    for (int n = 0; n < 8; n++)
        g_ybp[((size_t)ch * BB + b) * (NH * HH) + n * HH + h] = acc[n];
}

// ---------------- k_ovav: reduce + normalize + V-proj + O-proj partial --------
// grid 64 = (b, n), 512 threads
__global__ void __launch_bounds__(512) k_ovav(const float* __restrict__ wv,
                                              const float* __restrict__ wo) {
    __shared__ float part[HH];
    __shared__ __align__(16) float ybs[HH];
    __shared__ __align__(16) float os32[DD];
    __shared__ float zinv_s;
    int tid = threadIdx.x, lane = tid & 31, warp = tid >> 5;
    int bn = blockIdx.x;
    int b = bn >> 3, n = bn & 7;

    // partition function: 64 chunk partials
    if (warp == 0) {
        float z = g_zp[(size_t)bn * NCH + lane] + g_zp[(size_t)bn * NCH + 32 + lane];
        #pragma unroll
        for (int off = 16; off; off >>= 1) z += __shfl_xor_sync(~0u, z, off);
        if (lane == 0) zinv_s = 1.f / z;
    }

    // reduce ybp: 2 groups x 32 chunks, 8-deep batched
    int h = tid & 255, g2 = tid >> 8;
    float s = 0.f;
    #pragma unroll
    for (int rr = 0; rr < 4; rr++) {
        float v[8];
        #pragma unroll
        for (int j = 0; j < 8; j++) {
            int c = g2 * 32 + rr * 8 + j;
            v[j] = g_ybp[((size_t)c * BB + b) * (NH * HH) + n * HH + h];
        }
        #pragma unroll
        for (int j = 0; j < 8; j++) s += v[j];
    }
    if (g2 == 1) part[h] = s;
    __syncthreads();
    if (g2 == 0) ybs[h] = (s + part[h]) * zinv_s;
    __syncthreads();

    // V projection: o_slice[k] = ybs . wv[n*32+k, :], 16 threads per row
    {
        int k = tid >> 4, g = tid & 15;
        const float4* wvr = (const float4*)(wv + (size_t)(n * DD + k) * HH);
        const float4* yb4 = (const float4*)ybs;
        float a = 0.f;
        #pragma unroll
        for (int c = 0; c < 4; c++) {
            float4 w = wvr[g * 4 + c]; float4 y = yb4[g * 4 + c];
            a += w.x * y.x + w.y * y.y + w.z * y.z + w.w * y.w;
        }
        a += __shfl_xor_sync(~0u, a, 8);
        a += __shfl_xor_sync(~0u, a, 4);
        a += __shfl_xor_sync(~0u, a, 2);
        a += __shfl_xor_sync(~0u, a, 1);
        if (g == 0) os32[k] = a;
    }
    __syncthreads();

    // O-projection partial: yfin[b,h] += wo[h, n*32:(n+1)*32] . os32
    // 2 threads per h (split k in halves), 512 threads -> 256 h
    {
        int hh = tid >> 1, half = tid & 1;
        const float4* wor = (const float4*)(wo + (size_t)hh * HH + n * DD) + half * 4;
        const float4* o4 = (const float4*)os32 + half * 4;
        float a = 0.f;
        #pragma unroll
        for (int c = 0; c < 4; c++) {
            float4 w = wor[c]; float4 o = o4[c];
            a += w.x * o.x + w.y * o.y + w.z * o.z + w.w * o.w;
        }
        a += __shfl_xor_sync(~0u, a, 1);
        if (half == 0) atomicAdd(&g_yfin[b * HH + hh], a);
    }
}

// ---------------- k_out: out[b, v] = yfin[b] . wu[v] --------------------------
// 8 lanes per vocab row (coalesced 128B groups), 32 rows per 256-thread block.
// Inner product restructured: c outer, b inner -> 8 independent FFMA chains.
__global__ void __launch_bounds__(256) k_out(const float* __restrict__ wu,
                                             float* __restrict__ out) {
    __shared__ __align__(16) float yf[BB * HH];   // 8 KB
    int tid = threadIdx.x;
    for (int i = tid; i < BB * HH; i += 256) yf[i] = g_yfin[i];
    __syncthreads();

    int v = blockIdx.x * 32 + (tid >> 3);
    int g = tid & 7;
    if (v >= VV) return;

    // prefetch this lane's 8 wu float4 (coalesced: lanes g=0..7 consecutive)
    const float4* wur = (const float4*)(wu + (size_t)v * HH);
    float4 w[8];
    #pragma unroll
    for (int c = 0; c < 8; c++) w[c] = wur[c * 8 + g];

    const float4* yf4 = (const float4*)yf;
    float acc[8] = {0.f, 0.f, 0.f, 0.f, 0.f, 0.f, 0.f, 0.f};
    #pragma unroll
    for (int c = 0; c < 8; c++) {
        // batch-load 8 y vectors (independent LDS), then 8 independent FMA chains
        float4 y[8];
        #pragma unroll
        for (int b = 0; b < 8; b++) y[b] = yf4[b * 64 + c * 8 + g];
        #pragma unroll
        for (int b = 0; b < 8; b++) {
            acc[b] += w[c].x * y[b].x + w[c].y * y[b].y
                    + w[c].z * y[b].z + w[c].w * y[b].w;
        }
    }

    // funnel reduce across the 8 lanes of the group: 3 value-folding stages.
    #pragma unroll
    for (int i = 0; i < 4; i++) {
        bool hi = (g & 4) != 0;
        float keep = hi ? acc[i + 4] : acc[i];
        float send = hi ? acc[i] : acc[i + 4];
        acc[i] = keep + __shfl_xor_sync(0xffffffffu, send, 4);
    }
    #pragma unroll
    for (int i = 0; i < 2; i++) {
        bool hi = (g & 2) != 0;
        float keep = hi ? acc[i + 2] : acc[i];
        float send = hi ? acc[i] : acc[i + 2];
        acc[i] = keep + __shfl_xor_sync(0xffffffffu, send, 2);
    }
    {
        bool hi = (g & 1) != 0;
        float keep = hi ? acc[1] : acc[0];
        float send = hi ? acc[0] : acc[1];
        acc[0] = keep + __shfl_xor_sync(0xffffffffu, send, 1);
    }
    // lane g of the group now holds batch b = g
    out[(size_t)g * VV + v] = acc[0];
}

// ---------------- launcher ----------------------------------------------------
extern "C" void kernel_launch(void* const* d_in, const int* in_sizes, int n_in,
                              void* d_out, int out_size) {
    const void*  x   = d_in[0];
    const float* emb = (const float*)d_in[1];
    const float* wq  = (const float*)d_in[2];
    const float* wk  = (const float*)d_in[3];
    const float* wv  = (const float*)d_in[4];
    const float* wo  = (const float*)d_in[5];
    const float* wu  = (const float*)d_in[6];
    float* out = (float*)d_out;

    k_init<<<NH + 1, 256>>>((const unsigned int*)x, emb, wq, wk);
    k_ybar<<<dim3(NCH, BB), 256>>>(x, emb);
    k_ovav<<<BB * NH, 512>>>(wv, wo);
    k_out<<<(VV + 31) / 32, 256>>>(wu, out);
}

// round 16
// speedup vs baseline: 1.0417x; 1.0417x over previous
#include <cuda_runtime.h>

// Problem constants
#define BB   8
#define SEQ  2047
#define LL   2048     // SEQ + 1 (CLS prepended)
#define HH   256
#define NH   8
#define DD   32
#define VV   32001
#define NCH  64       // t-chunks for ybar
#define CHT  32       // tokens per chunk

// ---------------- scratch (static device globals; no allocation) -------------
__device__ int   g_is64;
__device__ float g_qk[NH * HH];                 // per-head folded query vectors (scaled)
__device__ float g_zp[BB * NH * NCH];           // partition-function partials
__device__ float g_ybp[NCH * BB * NH * HH];     // weighted-sum partials (4 MB)
__device__ float g_yfin[BB * HH];               // final hidden at position 0 (accum)

// ---------------- k_init: dtype detect (block 8) + per-head qk (blocks 0-7) --
// Block n also seeds g_yfin[b=n] with the 2*y0 residual (atomic target).
__global__ void __launch_bounds__(256) k_init(const unsigned int* __restrict__ xw,
                                              const float* __restrict__ emb,
                                              const float* __restrict__ wq,
                                              const float* __restrict__ wk) {
    int blk = blockIdx.x;
    int tid = threadIdx.x;

    if (blk == NH) {             // ---- dtype detection ----
        __shared__ int bad;
        if (tid == 0) bad = 0;
        __syncthreads();
        for (int i = tid; i < 1024; i += 256)
            if (xw[2 * i + 1] != 0u) bad = 1;
        __syncthreads();
        if (tid == 0) g_is64 = bad ? 0 : 1;
        return;
    }

    int n = blk;
    __shared__ float y0s[HH];
    __shared__ float q0s[DD];

    float y0 = emb[2 * HH + tid] + ((tid & 1) ? 1.0f : 0.0f);   // pe[0]=[0,1,0,1..]
    y0s[tid] = y0;
    g_yfin[n * HH + tid] = 2.f * y0;      // seed residual for batch b=n
    __syncthreads();

    if (tid < DD) {
        const float* wqr = wq + (size_t)(n * DD + tid) * HH;
        float a = 0.f;
        #pragma unroll 8
        for (int h = 0; h < HH; h++) a += y0s[h] * wqr[h];
        q0s[tid] = a;
    }
    __syncthreads();

    const float scale = 0.17677669529663687f;   // 1/sqrt(32)
    float s = 0.f;
    #pragma unroll
    for (int k = 0; k < DD; k++)
        s += q0s[k] * wk[(size_t)(n * DD + k) * HH + tid];
    g_qk[n * HH + tid] = s * scale;
}

// ---------------- k_ybar: gather y (emb + inline PE), scores+exp, Z, sums -----
// grid (NCH=64 chunks, BB batches), 256 threads; ~42 KB smem
__global__ void __launch_bounds__(256) k_ybar(const void* __restrict__ xraw,
                                              const float* __restrict__ emb) {
    __shared__ __align__(16) float ys[CHT * HH];   // 32 KB: y = emb[tok] + pe
    __shared__ __align__(16) float qks[NH * HH];   // 8 KB
    __shared__ __align__(16) float A8[NH][CHT];    // 1 KB unnormalized probs
    __shared__ int toks[CHT];
    int tid = threadIdx.x, lane = tid & 31, warp = tid >> 5;
    int ch = blockIdx.x;
    int b  = blockIdx.y;
    int c0 = ch * CHT;
    int is64 = g_is64;

    for (int i = tid; i < NH * HH; i += 256) qks[i] = g_qk[i];
    if (tid < CHT) {
        int t = c0 + tid;
        int tok;
        if (t == 0) tok = 2;
        else if (is64) tok = (int)((const long long*)xraw)[(size_t)b * SEQ + t - 1];
        else           tok = ((const int*)xraw)[(size_t)b * SEQ + t - 1];
        toks[tid] = tok;
    }
    __syncthreads();

    // Phase A: gather emb rows + compute PE inline (coalesced float4)
    {
        const float4* emb4 = (const float4*)emb;
        float4* ys4        = (float4*)ys;
        const float KK = 0.03597789203f;    // ln(10000)/256
        int q = tid & 63;
        float d0 = expf(-(float)(4 * q)     * KK);
        float d1 = expf(-(float)(4 * q + 2) * KK);
        #pragma unroll
        for (int j = tid; j < CHT * 64; j += 256) {
            int r = j >> 6;
            float4 e = emb4[(size_t)toks[r] * 64 + q];
            float t = (float)(c0 + r);
            float s0, cc0, s1, cc1;
            sincosf(t * d0, &s0, &cc0);
            sincosf(t * d1, &s1, &cc1);
            e.x += s0; e.y += cc0; e.z += s1; e.w += cc1;
            ys4[j] = e;
        }
    }
    __syncthreads();

    // Phase B: scores + exp. Warp w handles tokens w*4..w*4+3, all 8 heads.
    {
        const float4* ysq = (const float4*)ys;
        float4 av[4], bv[4];
        #pragma unroll
        for (int r = 0; r < 4; r++) {
            av[r] = ysq[(warp * 4 + r) * 64 + lane];
            bv[r] = ysq[(warp * 4 + r) * 64 + lane + 32];
        }
        float p[4][8];
        #pragma unroll
        for (int n = 0; n < 8; n++) {
            const float4* q4 = (const float4*)(qks + n * HH);
            float4 qa = q4[lane], qb = q4[lane + 32];
            #pragma unroll
            for (int r = 0; r < 4; r++) {
                p[r][n] = av[r].x * qa.x + av[r].y * qa.y + av[r].z * qa.z + av[r].w * qa.w
                        + bv[r].x * qb.x + bv[r].y * qb.y + bv[r].z * qb.z + bv[r].w * qb.w;
            }
        }
        #pragma unroll
        for (int r = 0; r < 4; r++) {
            #pragma unroll
            for (int n = 0; n < 4; n++) {
                bool hi = (lane & 8) != 0;
                float k = hi ? p[r][n + 4] : p[r][n];
                float s = hi ? p[r][n] : p[r][n + 4];
                p[r][n] = k + __shfl_xor_sync(~0u, s, 8);
            }
            #pragma unroll
            for (int n = 0; n < 2; n++) {
                bool hi = (lane & 4) != 0;
                float k = hi ? p[r][n + 2] : p[r][n];
                float s = hi ? p[r][n] : p[r][n + 2];
                p[r][n] = k + __shfl_xor_sync(~0u, s, 4);
            }
            {
                bool hi = (lane & 2) != 0;
                float k = hi ? p[r][1] : p[r][0];
                float s = hi ? p[r][0] : p[r][1];
                p[r][0] = k + __shfl_xor_sync(~0u, s, 2);
            }
            p[r][0] += __shfl_xor_sync(~0u, p[r][0], 16);
            p[r][0] += __shfl_xor_sync(~0u, p[r][0], 1);
        }
        int n_ = lane & 7, r_ = lane >> 3;
        float res[4];
        #pragma unroll
        for (int r = 0; r < 4; r++)
            res[r] = __shfl_sync(~0u, p[r][0], n_ * 2);
        A8[n_][warp * 4 + r_] = expf(res[r_]);
    }
    __syncthreads();

    // Phase Z: warp n reduces A8[n][:]
    {
        float z = A8[warp][lane];
        #pragma unroll
        for (int off = 16; off; off >>= 1) z += __shfl_xor_sync(~0u, z, off);
        if (lane == 0) g_zp[((size_t)b * NH + warp) * NCH + ch] = z;
    }

    // Phase C: weighted sums from smem (tid = h), float4 A8 loads
    int h = tid;
    float acc[8] = {0.f, 0.f, 0.f, 0.f, 0.f, 0.f, 0.f, 0.f};
    const float4* A84 = (const float4*)A8;
    #pragma unroll
    for (int tg = 0; tg < CHT / 4; tg++) {
        float4 a[8];
        #pragma unroll
        for (int n = 0; n < 8; n++) a[n] = A84[n * (CHT / 4) + tg];
        float y0v = ys[(tg * 4 + 0) * HH + h];
        float y1v = ys[(tg * 4 + 1) * HH + h];
        float y2v = ys[(tg * 4 + 2) * HH + h];
        float y3v = ys[(tg * 4 + 3) * HH + h];
        #pragma unroll
        for (int n = 0; n < 8; n++)
            acc[n] += a[n].x * y0v + a[n].y * y1v + a[n].z * y2v + a[n].w * y3v;
    }
    #pragma unroll
    for (int n = 0; n < 8; n++)
        g_ybp[((size_t)ch * BB + b) * (NH * HH) + n * HH + h] = acc[n];
}

// ---------------- k_ovav: reduce + normalize + V-proj + O-proj partial --------
// grid 64 = (b, n), 512 threads
__global__ void __launch_bounds__(512) k_ovav(const float* __restrict__ wv,
                                              const float* __restrict__ wo) {
    __shared__ float part[HH];
    __shared__ __align__(16) float ybs[HH];
    __shared__ __align__(16) float os32[DD];
    __shared__ float zinv_s;
    int tid = threadIdx.x, lane = tid & 31, warp = tid >> 5;
    int bn = blockIdx.x;
    int b = bn >> 3, n = bn & 7;

    // partition function: 64 chunk partials
    if (warp == 0) {
        float z = g_zp[(size_t)bn * NCH + lane] + g_zp[(size_t)bn * NCH + 32 + lane];
        #pragma unroll
        for (int off = 16; off; off >>= 1) z += __shfl_xor_sync(~0u, z, off);
        if (lane == 0) zinv_s = 1.f / z;
    }

    // reduce ybp: 2 groups x 32 chunks, 8-deep batched
    int h = tid & 255, g2 = tid >> 8;
    float s = 0.f;
    #pragma unroll
    for (int rr = 0; rr < 4; rr++) {
        float v[8];
        #pragma unroll
        for (int j = 0; j < 8; j++) {
            int c = g2 * 32 + rr * 8 + j;
            v[j] = g_ybp[((size_t)c * BB + b) * (NH * HH) + n * HH + h];
        }
        #pragma unroll
        for (int j = 0; j < 8; j++) s += v[j];
    }
    if (g2 == 1) part[h] = s;
    __syncthreads();
    if (g2 == 0) ybs[h] = (s + part[h]) * zinv_s;
    __syncthreads();

    // V projection: o_slice[k] = ybs . wv[n*32+k, :], 16 threads per row
    {
        int k = tid >> 4, g = tid & 15;
        const float4* wvr = (const float4*)(wv + (size_t)(n * DD + k) * HH);
        const float4* yb4 = (const float4*)ybs;
        float a = 0.f;
        #pragma unroll
        for (int c = 0; c < 4; c++) {
            float4 w = wvr[g * 4 + c]; float4 y = yb4[g * 4 + c];
            a += w.x * y.x + w.y * y.y + w.z * y.z + w.w * y.w;
        }
        a += __shfl_xor_sync(~0u, a, 8);
        a += __shfl_xor_sync(~0u, a, 4);
        a += __shfl_xor_sync(~0u, a, 2);
        a += __shfl_xor_sync(~0u, a, 1);
        if (g == 0) os32[k] = a;
    }
    __syncthreads();

    // O-projection partial: yfin[b,h] += wo[h, n*32:(n+1)*32] . os32
    // 2 threads per h (split k in halves), 512 threads -> 256 h
    {
        int hh = tid >> 1, half = tid & 1;
        const float4* wor = (const float4*)(wo + (size_t)hh * HH + n * DD) + half * 4;
        const float4* o4 = (const float4*)os32 + half * 4;
        float a = 0.f;
        #pragma unroll
        for (int c = 0; c < 4; c++) {
            float4 w = wor[c]; float4 o = o4[c];
            a += w.x * o.x + w.y * o.y + w.z * o.z + w.w * o.w;
        }
        a += __shfl_xor_sync(~0u, a, 1);
        if (half == 0) atomicAdd(&g_yfin[b * HH + hh], a);
    }
}

// ---------------- k_out: out[b, v] = yfin[b] . wu[v] --------------------------
// 8 lanes per vocab row-pair; each thread handles 2 rows (v0, v0+1) so every
// yf LDS feeds 16 FMAs instead of 8 (halves smem crossbar traffic).
// 64 rows per 256-thread block -> grid 501.
__global__ void __launch_bounds__(256) k_out(const float* __restrict__ wu,
                                             float* __restrict__ out) {
    __shared__ __align__(16) float yf[BB * HH];   // 8 KB
    int tid = threadIdx.x;
    for (int i = tid; i < BB * HH; i += 256) yf[i] = g_yfin[i];
    __syncthreads();

    int rg = tid >> 3;          // row-group 0..31
    int g  = tid & 7;
    int v0 = blockIdx.x * 64 + rg * 2;
    int v1 = v0 + 1;
    if (v0 >= VV) return;
    bool has1 = (v1 < VV);

    // prefetch both rows' wu slices (coalesced: lanes g=0..7 consecutive)
    const float4* wur0 = (const float4*)(wu + (size_t)v0 * HH);
    const float4* wur1 = (const float4*)(wu + (size_t)(has1 ? v1 : v0) * HH);
    float4 w0[8], w1[8];
    #pragma unroll
    for (int c = 0; c < 8; c++) w0[c] = wur0[c * 8 + g];
    #pragma unroll
    for (int c = 0; c < 8; c++) w1[c] = wur1[c * 8 + g];

    const float4* yf4 = (const float4*)yf;
    float acc0[8] = {0.f, 0.f, 0.f, 0.f, 0.f, 0.f, 0.f, 0.f};
    float acc1[8] = {0.f, 0.f, 0.f, 0.f, 0.f, 0.f, 0.f, 0.f};
    #pragma unroll
    for (int c = 0; c < 8; c++) {
        float4 y[8];
        #pragma unroll
        for (int b = 0; b < 8; b++) y[b] = yf4[b * 64 + c * 8 + g];
        #pragma unroll
        for (int b = 0; b < 8; b++) {
            acc0[b] += w0[c].x * y[b].x + w0[c].y * y[b].y
                     + w0[c].z * y[b].z + w0[c].w * y[b].w;
            acc1[b] += w1[c].x * y[b].x + w1[c].y * y[b].y
                     + w1[c].z * y[b].z + w1[c].w * y[b].w;
        }
    }

    // funnel reduce each row's 8 accumulators across the 8 lanes (3 stages).
    #pragma unroll
    for (int i = 0; i < 4; i++) {
        bool hi = (g & 4) != 0;
        float k0 = hi ? acc0[i + 4] : acc0[i], s0 = hi ? acc0[i] : acc0[i + 4];
        float k1 = hi ? acc1[i + 4] : acc1[i], s1 = hi ? acc1[i] : acc1[i + 4];
        acc0[i] = k0 + __shfl_xor_sync(0xffffffffu, s0, 4);
        acc1[i] = k1 + __shfl_xor_sync(0xffffffffu, s1, 4);
    }
    #pragma unroll
    for (int i = 0; i < 2; i++) {
        bool hi = (g & 2) != 0;
        float k0 = hi ? acc0[i + 2] : acc0[i], s0 = hi ? acc0[i] : acc0[i + 2];
        float k1 = hi ? acc1[i + 2] : acc1[i], s1 = hi ? acc1[i] : acc1[i + 2];
        acc0[i] = k0 + __shfl_xor_sync(0xffffffffu, s0, 2);
        acc1[i] = k1 + __shfl_xor_sync(0xffffffffu, s1, 2);
    }
    {
        bool hi = (g & 1) != 0;
        float k0 = hi ? acc0[1] : acc0[0], s0 = hi ? acc0[0] : acc0[1];
        float k1 = hi ? acc1[1] : acc1[0], s1 = hi ? acc1[0] : acc1[1];
        acc0[0] = k0 + __shfl_xor_sync(0xffffffffu, s0, 1);
        acc1[0] = k1 + __shfl_xor_sync(0xffffffffu, s1, 1);
    }
    // lane g of the group now holds batch b = g for both rows
    out[(size_t)g * VV + v0] = acc0[0];
    if (has1) out[(size_t)g * VV + v1] = acc1[0];
}

// ---------------- launcher ----------------------------------------------------
extern "C" void kernel_launch(void* const* d_in, const int* in_sizes, int n_in,
                              void* d_out, int out_size) {
    const void*  x   = d_in[0];
    const float* emb = (const float*)d_in[1];
    const float* wq  = (const float*)d_in[2];
    const float* wk  = (const float*)d_in[3];
    const float* wv  = (const float*)d_in[4];
    const float* wo  = (const float*)d_in[5];
    const float* wu  = (const float*)d_in[6];
    float* out = (float*)d_out;

    k_init<<<NH + 1, 256>>>((const unsigned int*)x, emb, wq, wk);
    k_ybar<<<dim3(NCH, BB), 256>>>(x, emb);
    k_ovav<<<BB * NH, 512>>>(wv, wo);
    k_out<<<(VV + 63) / 64, 256>>>(wu, out);
}

// round 17
// speedup vs baseline: 1.0929x; 1.0491x over previous
#include <cuda_runtime.h>

// Problem constants
#define BB   8
#define SEQ  2047
#define LL   2048     // SEQ + 1 (CLS prepended)
#define HH   256
#define NH   8
#define DD   32
#define VV   32001
#define NCH  64       // t-chunks for ybar
#define CHT  32       // tokens per chunk

// ---------------- scratch (static device globals; no allocation) -------------
__device__ int   g_is64;
__device__ float g_qk[NH * HH];                 // per-head folded query vectors (scaled)
__device__ float g_zp[BB * NH * NCH];           // partition-function partials
__device__ float g_ybp[NCH * BB * NH * HH];     // weighted-sum partials (4 MB)
__device__ float g_yfin[BB * HH];               // final hidden at position 0 (accum)

// ---------------- k_init: dtype detect (block 8) + per-head qk (blocks 0-7) --
// Block n also seeds g_yfin[b=n] with the 2*y0 residual (atomic target).
__global__ void __launch_bounds__(256) k_init(const unsigned int* __restrict__ xw,
                                              const float* __restrict__ emb,
                                              const float* __restrict__ wq,
                                              const float* __restrict__ wk) {
    int blk = blockIdx.x;
    int tid = threadIdx.x;

    if (blk == NH) {             // ---- dtype detection ----
        __shared__ int bad;
        if (tid == 0) bad = 0;
        __syncthreads();
        for (int i = tid; i < 1024; i += 256)
            if (xw[2 * i + 1] != 0u) bad = 1;
        __syncthreads();
        if (tid == 0) g_is64 = bad ? 0 : 1;
        return;
    }

    int n = blk;
    __shared__ float y0s[HH];
    __shared__ float q0s[DD];

    float y0 = emb[2 * HH + tid] + ((tid & 1) ? 1.0f : 0.0f);   // pe[0]=[0,1,0,1..]
    y0s[tid] = y0;
    g_yfin[n * HH + tid] = 2.f * y0;      // seed residual for batch b=n
    __syncthreads();

    if (tid < DD) {
        const float* wqr = wq + (size_t)(n * DD + tid) * HH;
        float a = 0.f;
        #pragma unroll 8
        for (int h = 0; h < HH; h++) a += y0s[h] * wqr[h];
        q0s[tid] = a;
    }
    __syncthreads();

    const float scale = 0.17677669529663687f;   // 1/sqrt(32)
    float s = 0.f;
    #pragma unroll
    for (int k = 0; k < DD; k++)
        s += q0s[k] * wk[(size_t)(n * DD + k) * HH + tid];
    g_qk[n * HH + tid] = s * scale;
}

// ---------------- k_ybar: gather y (emb + inline PE), scores+exp, Z, sums -----
// grid (NCH=64 chunks, BB batches), 256 threads; ~42 KB smem
__global__ void __launch_bounds__(256) k_ybar(const void* __restrict__ xraw,
                                              const float* __restrict__ emb) {
    __shared__ __align__(16) float ys[CHT * HH];   // 32 KB: y = emb[tok] + pe
    __shared__ __align__(16) float qks[NH * HH];   // 8 KB
    __shared__ __align__(16) float A8[NH][CHT];    // 1 KB unnormalized probs
    __shared__ int toks[CHT];
    int tid = threadIdx.x, lane = tid & 31, warp = tid >> 5;
    int ch = blockIdx.x;
    int b  = blockIdx.y;
    int c0 = ch * CHT;
    int is64 = g_is64;

    for (int i = tid; i < NH * HH; i += 256) qks[i] = g_qk[i];
    if (tid < CHT) {
        int t = c0 + tid;
        int tok;
        if (t == 0) tok = 2;
        else if (is64) tok = (int)((const long long*)xraw)[(size_t)b * SEQ + t - 1];
        else           tok = ((const int*)xraw)[(size_t)b * SEQ + t - 1];
        toks[tid] = tok;
    }
    __syncthreads();

    // Phase A: gather emb rows + compute PE inline (coalesced float4)
    {
        const float4* emb4 = (const float4*)emb;
        float4* ys4        = (float4*)ys;
        const float KK = 0.03597789203f;    // ln(10000)/256
        int q = tid & 63;
        float d0 = expf(-(float)(4 * q)     * KK);
        float d1 = expf(-(float)(4 * q + 2) * KK);
        #pragma unroll
        for (int j = tid; j < CHT * 64; j += 256) {
            int r = j >> 6;
            float4 e = emb4[(size_t)toks[r] * 64 + q];
            float t = (float)(c0 + r);
            float s0, cc0, s1, cc1;
            sincosf(t * d0, &s0, &cc0);
            sincosf(t * d1, &s1, &cc1);
            e.x += s0; e.y += cc0; e.z += s1; e.w += cc1;
            ys4[j] = e;
        }
    }
    __syncthreads();

    // Phase B: scores + exp. Warp w handles tokens w*4..w*4+3, all 8 heads.
    {
        const float4* ysq = (const float4*)ys;
        float4 av[4], bv[4];
        #pragma unroll
        for (int r = 0; r < 4; r++) {
            av[r] = ysq[(warp * 4 + r) * 64 + lane];
            bv[r] = ysq[(warp * 4 + r) * 64 + lane + 32];
        }
        float p[4][8];
        #pragma unroll
        for (int n = 0; n < 8; n++) {
            const float4* q4 = (const float4*)(qks + n * HH);
            float4 qa = q4[lane], qb = q4[lane + 32];
            #pragma unroll
            for (int r = 0; r < 4; r++) {
                p[r][n] = av[r].x * qa.x + av[r].y * qa.y + av[r].z * qa.z + av[r].w * qa.w
                        + bv[r].x * qb.x + bv[r].y * qb.y + bv[r].z * qb.z + bv[r].w * qb.w;
            }
        }
        #pragma unroll
        for (int r = 0; r < 4; r++) {
            #pragma unroll
            for (int n = 0; n < 4; n++) {
                bool hi = (lane & 8) != 0;
                float k = hi ? p[r][n + 4] : p[r][n];
                float s = hi ? p[r][n] : p[r][n + 4];
                p[r][n] = k + __shfl_xor_sync(~0u, s, 8);
            }
            #pragma unroll
            for (int n = 0; n < 2; n++) {
                bool hi = (lane & 4) != 0;
                float k = hi ? p[r][n + 2] : p[r][n];
                float s = hi ? p[r][n] : p[r][n + 2];
                p[r][n] = k + __shfl_xor_sync(~0u, s, 4);
            }
            {
                bool hi = (lane & 2) != 0;
                float k = hi ? p[r][1] : p[r][0];
                float s = hi ? p[r][0] : p[r][1];
                p[r][0] = k + __shfl_xor_sync(~0u, s, 2);
            }
            p[r][0] += __shfl_xor_sync(~0u, p[r][0], 16);
            p[r][0] += __shfl_xor_sync(~0u, p[r][0], 1);
        }
        int n_ = lane & 7, r_ = lane >> 3;
        float res[4];
        #pragma unroll
        for (int r = 0; r < 4; r++)
            res[r] = __shfl_sync(~0u, p[r][0], n_ * 2);
        A8[n_][warp * 4 + r_] = expf(res[r_]);
    }
    __syncthreads();

    // Phase Z: warp n reduces A8[n][:]
    {
        float z = A8[warp][lane];
        #pragma unroll
        for (int off = 16; off; off >>= 1) z += __shfl_xor_sync(~0u, z, off);
        if (lane == 0) g_zp[((size_t)b * NH + warp) * NCH + ch] = z;
    }

    // Phase C: weighted sums from smem (tid = h), float4 A8 loads
    int h = tid;
    float acc[8] = {0.f, 0.f, 0.f, 0.f, 0.f, 0.f, 0.f, 0.f};
    const float4* A84 = (const float4*)A8;
    #pragma unroll
    for (int tg = 0; tg < CHT / 4; tg++) {
        float4 a[8];
        #pragma unroll
        for (int n = 0; n < 8; n++) a[n] = A84[n * (CHT / 4) + tg];
        float y0v = ys[(tg * 4 + 0) * HH + h];
        float y1v = ys[(tg * 4 + 1) * HH + h];
        float y2v = ys[(tg * 4 + 2) * HH + h];
        float y3v = ys[(tg * 4 + 3) * HH + h];
        #pragma unroll
        for (int n = 0; n < 8; n++)
            acc[n] += a[n].x * y0v + a[n].y * y1v + a[n].z * y2v + a[n].w * y3v;
    }
    #pragma unroll
    for (int n = 0; n < 8; n++)
        g_ybp[((size_t)ch * BB + b) * (NH * HH) + n * HH + h] = acc[n];
}

// ---------------- k_ovav: reduce + normalize + V-proj + O-proj partial --------
// grid 64 = (b, n), 512 threads
__global__ void __launch_bounds__(512) k_ovav(const float* __restrict__ wv,
                                              const float* __restrict__ wo) {
    __shared__ float part[HH];
    __shared__ __align__(16) float ybs[HH];
    __shared__ __align__(16) float os32[DD];
    __shared__ float zinv_s;
    int tid = threadIdx.x, lane = tid & 31, warp = tid >> 5;
    int bn = blockIdx.x;
    int b = bn >> 3, n = bn & 7;

    // partition function: 64 chunk partials
    if (warp == 0) {
        float z = g_zp[(size_t)bn * NCH + lane] + g_zp[(size_t)bn * NCH + 32 + lane];
        #pragma unroll
        for (int off = 16; off; off >>= 1) z += __shfl_xor_sync(~0u, z, off);
        if (lane == 0) zinv_s = 1.f / z;
    }

    // reduce ybp: 2 groups x 32 chunks, 8-deep batched
    int h = tid & 255, g2 = tid >> 8;
    float s = 0.f;
    #pragma unroll
    for (int rr = 0; rr < 4; rr++) {
        float v[8];
        #pragma unroll
        for (int j = 0; j < 8; j++) {
            int c = g2 * 32 + rr * 8 + j;
            v[j] = g_ybp[((size_t)c * BB + b) * (NH * HH) + n * HH + h];
        }
        #pragma unroll
        for (int j = 0; j < 8; j++) s += v[j];
    }
    if (g2 == 1) part[h] = s;
    __syncthreads();
    if (g2 == 0) ybs[h] = (s + part[h]) * zinv_s;
    __syncthreads();

    // V projection: o_slice[k] = ybs . wv[n*32+k, :], 16 threads per row
    {
        int k = tid >> 4, g = tid & 15;
        const float4* wvr = (const float4*)(wv + (size_t)(n * DD + k) * HH);
        const float4* yb4 = (const float4*)ybs;
        float a = 0.f;
        #pragma unroll
        for (int c = 0; c < 4; c++) {
            float4 w = wvr[g * 4 + c]; float4 y = yb4[g * 4 + c];
            a += w.x * y.x + w.y * y.y + w.z * y.z + w.w * y.w;
        }
        a += __shfl_xor_sync(~0u, a, 8);
        a += __shfl_xor_sync(~0u, a, 4);
        a += __shfl_xor_sync(~0u, a, 2);
        a += __shfl_xor_sync(~0u, a, 1);
        if (g == 0) os32[k] = a;
    }
    __syncthreads();

    // O-projection partial: yfin[b,h] += wo[h, n*32:(n+1)*32] . os32
    // 2 threads per h (split k in halves), 512 threads -> 256 h
    {
        int hh = tid >> 1, half = tid & 1;
        const float4* wor = (const float4*)(wo + (size_t)hh * HH + n * DD) + half * 4;
        const float4* o4 = (const float4*)os32 + half * 4;
        float a = 0.f;
        #pragma unroll
        for (int c = 0; c < 4; c++) {
            float4 w = wor[c]; float4 o = o4[c];
            a += w.x * o.x + w.y * o.y + w.z * o.z + w.w * o.w;
        }
        a += __shfl_xor_sync(~0u, a, 1);
        if (half == 0) atomicAdd(&g_yfin[b * HH + hh], a);
    }
}

// ---------------- k_out: out[b, v] = yfin[b] . wu[v] --------------------------
// 8 lanes per vocab row; each thread handles 4 rows so every yf LDS feeds
// 32 FMAs (quarter smem crossbar traffic vs 1 row/thread).
// 128 rows per 256-thread block -> grid 251.
__global__ void __launch_bounds__(256) k_out(const float* __restrict__ wu,
                                             float* __restrict__ out) {
    __shared__ __align__(16) float yf[BB * HH];   // 8 KB
    int tid = threadIdx.x;
    for (int i = tid; i < BB * HH; i += 256) yf[i] = g_yfin[i];
    __syncthreads();

    int rg = tid >> 3;          // row-group 0..31
    int g  = tid & 7;
    int v0 = blockIdx.x * 128 + rg * 4;
    if (v0 >= VV) return;

    // row pointers (clamped; results for OOB rows discarded at store)
    const float4* wur[4];
    #pragma unroll
    for (int r = 0; r < 4; r++) {
        int v = v0 + r < VV ? v0 + r : v0;
        wur[r] = (const float4*)(wu + (size_t)v * HH);
    }

    const float4* yf4 = (const float4*)yf;
    float acc[4][8];
    #pragma unroll
    for (int r = 0; r < 4; r++)
        #pragma unroll
        for (int b = 0; b < 8; b++) acc[r][b] = 0.f;

    #pragma unroll
    for (int c = 0; c < 8; c++) {
        // 4 coalesced wu loads + 8 yf LDS per step (all independent)
        float4 w[4];
        #pragma unroll
        for (int r = 0; r < 4; r++) w[r] = wur[r][c * 8 + g];
        float4 y[8];
        #pragma unroll
        for (int b = 0; b < 8; b++) y[b] = yf4[b * 64 + c * 8 + g];
        #pragma unroll
        for (int r = 0; r < 4; r++) {
            #pragma unroll
            for (int b = 0; b < 8; b++) {
                acc[r][b] += w[r].x * y[b].x + w[r].y * y[b].y
                           + w[r].z * y[b].z + w[r].w * y[b].w;
            }
        }
    }

    // funnel reduce each row's 8 accumulators across the 8 lanes (3 stages).
    #pragma unroll
    for (int r = 0; r < 4; r++) {
        #pragma unroll
        for (int i = 0; i < 4; i++) {
            bool hi = (g & 4) != 0;
            float k = hi ? acc[r][i + 4] : acc[r][i];
            float s = hi ? acc[r][i] : acc[r][i + 4];
            acc[r][i] = k + __shfl_xor_sync(0xffffffffu, s, 4);
        }
        #pragma unroll
        for (int i = 0; i < 2; i++) {
            bool hi = (g & 2) != 0;
            float k = hi ? acc[r][i + 2] : acc[r][i];
            float s = hi ? acc[r][i] : acc[r][i + 2];
            acc[r][i] = k + __shfl_xor_sync(0xffffffffu, s, 2);
        }
        {
            bool hi = (g & 1) != 0;
            float k = hi ? acc[r][1] : acc[r][0];
            float s = hi ? acc[r][0] : acc[r][1];
            acc[r][0] = k + __shfl_xor_sync(0xffffffffu, s, 1);
        }
    }
    // lane g of the group holds batch b = g for all 4 rows
    #pragma unroll
    for (int r = 0; r < 4; r++) {
        int v = v0 + r;
        if (v < VV) out[(size_t)g * VV + v] = acc[r][0];
    }
}

// ---------------- launcher ----------------------------------------------------
extern "C" void kernel_launch(void* const* d_in, const int* in_sizes, int n_in,
                              void* d_out, int out_size) {
    const void*  x   = d_in[0];
    const float* emb = (const float*)d_in[1];
    const float* wq  = (const float*)d_in[2];
    const float* wk  = (const float*)d_in[3];
    const float* wv  = (const float*)d_in[4];
    const float* wo  = (const float*)d_in[5];
    const float* wu  = (const float*)d_in[6];
    float* out = (float*)d_out;

    k_init<<<NH + 1, 256>>>((const unsigned int*)x, emb, wq, wk);
    k_ybar<<<dim3(NCH, BB), 256>>>(x, emb);
    k_ovav<<<BB * NH, 512>>>(wv, wo);
    k_out<<<(VV + 127) / 128, 256>>>(wu, out);
}